// round 1
// baseline (speedup 1.0000x reference)
#include <cuda_runtime.h>
#include <math.h>

#define Nn    50000
#define Ee    800000
#define LGEe  1600000
#define FNODE 256
#define Tt    64
#define HIDd  128
#define OUTd  64
#define SLOPE 0.2f

// ---------------- scratch (static device globals; no allocation) ----------------
__device__ float    B_deg_lg[Ee];
__device__ float    B_aggT[(size_t)Ee * Tt];       // 204.8 MB
__device__ float    B_h1[(size_t)Ee * HIDd];       // 409.6 MB
__device__ float    B_agg1[(size_t)Ee * HIDd];     // 409.6 MB
__device__ float    B_h2[(size_t)Ee * HIDd];       // 409.6 MB
__device__ float    B_deg_raw[Nn];
__device__ float    B_degN[Nn];
__device__ float    B_aggN[(size_t)Nn * HIDd];
__device__ float    B_tmp[(size_t)Nn * HIDd];
__device__ float    B_edge_repr[(size_t)Nn * HIDd];
__device__ float    B_aggr_edge[(size_t)Nn * HIDd];
__device__ float    B_xws[(size_t)Nn * HIDd];
__device__ float    B_xwn[(size_t)Nn * HIDd];
__device__ float    B_hn1[(size_t)Nn * HIDd];
__device__ float    B_hn2[(size_t)Nn * HIDd];
__device__ float    B_q[(size_t)Nn * HIDd];
__device__ float    B_k[(size_t)Nn * HIDd];
__device__ float    B_v[(size_t)Nn * HIDd];
__device__ float    B_attn[(size_t)Nn * HIDd];
__device__ float    B_score[Ee];
__device__ unsigned B_menc[Nn];
__device__ float    B_den[Nn];

// ---------------- small helpers ----------------
__device__ __forceinline__ unsigned flipf(float f) {
    unsigned u = __float_as_uint(f);
    unsigned mask = (u & 0x80000000u) ? 0xFFFFFFFFu : 0x80000000u;
    return u ^ mask;
}
__device__ __forceinline__ float unflipf(unsigned u) {
    unsigned mask = (u & 0x80000000u) ? 0x80000000u : 0xFFFFFFFFu;
    return __uint_as_float(u ^ mask);
}

// ---------------- zero fill ----------------
__global__ void zero_k(float* p, long n4) {
    long t = (long)blockIdx.x * blockDim.x + threadIdx.x;
    if (t < n4) ((float4*)p)[t] = make_float4(0.f, 0.f, 0.f, 0.f);
}

// ---------------- line-graph aggregation of et (T=64) + deg ----------------
__global__ void lg_agg64_k(const int* __restrict__ src, const int* __restrict__ dst,
                           const float* __restrict__ et, float* __restrict__ agg,
                           float* __restrict__ deg) {
    long t = (long)blockIdx.x * blockDim.x + threadIdx.x;
    int e = (int)(t >> 4), c = (int)(t & 15);
    if (e >= LGEe) return;
    int s = src[e], d = dst[e];
    float4 v = *(const float4*)(et + (size_t)s * Tt + c * 4);
    float* o = agg + (size_t)d * Tt + c * 4;
    atomicAdd(o + 0, v.x); atomicAdd(o + 1, v.y);
    atomicAdd(o + 2, v.z); atomicAdd(o + 3, v.w);
    if (c == 0) atomicAdd(deg + d, 1.0f);
}

// ---------------- generic 128-wide gather/scatter-add aggregation ----------------
__global__ void agg128_k(const int* __restrict__ src, const int* __restrict__ dst,
                         const float* __restrict__ h, float* __restrict__ agg, int nE) {
    long t = (long)blockIdx.x * blockDim.x + threadIdx.x;
    int e = (int)(t >> 5), c = (int)(t & 31);
    if (e >= nE) return;
    int s = src[e], d = dst[e];
    float4 v = *(const float4*)(h + (size_t)s * HIDd + c * 4);
    float* o = agg + (size_t)d * HIDd + c * 4;
    atomicAdd(o + 0, v.x); atomicAdd(o + 1, v.y);
    atomicAdd(o + 2, v.z); atomicAdd(o + 3, v.w);
}

// ---------------- edge->node scatter to both endpoints ----------------
__global__ void e2n_agg_k(const int* __restrict__ h0, const int* __restrict__ h1,
                          const float* __restrict__ h2, float* __restrict__ agg,
                          float* __restrict__ deg) {
    long t = (long)blockIdx.x * blockDim.x + threadIdx.x;
    int e = (int)(t >> 5), c = (int)(t & 31);
    if (e >= Ee) return;
    int a = h0[e], b = h1[e];
    float4 v = *(const float4*)(h2 + (size_t)e * HIDd + c * 4);
    float* oa = agg + (size_t)a * HIDd + c * 4;
    float* ob = agg + (size_t)b * HIDd + c * 4;
    atomicAdd(oa + 0, v.x); atomicAdd(oa + 1, v.y);
    atomicAdd(oa + 2, v.z); atomicAdd(oa + 3, v.w);
    atomicAdd(ob + 0, v.x); atomicAdd(ob + 1, v.y);
    atomicAdd(ob + 2, v.z); atomicAdd(ob + 3, v.w);
    if (c == 0) { atomicAdd(deg + a, 1.0f); atomicAdd(deg + b, 1.0f); }
}

// ---------------- degree count on raw graph ----------------
__global__ void deg_k(const int* __restrict__ dst, float* __restrict__ deg, int nE) {
    int e = blockIdx.x * blockDim.x + threadIdx.x;
    if (e < nE) atomicAdd(deg + dst[e], 1.0f);
}

// ---------------- scale rows by 1/max(deg,1) ----------------
__global__ void scale_k(float* __restrict__ buf, const float* __restrict__ deg,
                        long rows, int D) {
    long t = (long)blockIdx.x * blockDim.x + threadIdx.x;
    long total = rows * (long)(D / 4);
    if (t >= total) return;
    long idx = t * 4;
    long r = idx / D;
    float inv = 1.0f / fmaxf(deg[r], 1.0f);
    float4 v = *(float4*)(buf + idx);
    v.x *= inv; v.y *= inv; v.z *= inv; v.w *= inv;
    *(float4*)(buf + idx) = v;
}

// ---------------- elementwise o = relu(a+b) ----------------
__global__ void addrelu_k(const float* __restrict__ a, const float* __restrict__ b,
                          float* __restrict__ o, long n4) {
    long t = (long)blockIdx.x * blockDim.x + threadIdx.x;
    if (t >= n4) return;
    float4 va = ((const float4*)a)[t], vb = ((const float4*)b)[t];
    float4 r;
    r.x = fmaxf(va.x + vb.x, 0.f); r.y = fmaxf(va.y + vb.y, 0.f);
    r.z = fmaxf(va.z + vb.z, 0.f); r.w = fmaxf(va.w + vb.w, 0.f);
    ((float4*)o)[t] = r;
}

// ---------------- tiled SGEMM:  C[M x 128] = [A0|A1] @ [W0;W1], fused epilogue ----------------
// 64x128 block tile, BK=16, 128 threads, 8x8 microtile per thread.
__device__ __forceinline__ float apply_epi(float v, int epi) {
    if (epi == 1) return fmaxf(v, 0.f);
    if (epi == 2) return v > 0.f ? v : SLOPE * v;
    return v;
}

__global__ void __launch_bounds__(128) gemm_k(
    const float* __restrict__ A0, int K0, const float* __restrict__ W0,
    const float* __restrict__ A1, int K1, const float* __restrict__ W1,
    float* __restrict__ C, int M, int epi)
{
    __shared__ float As[16][64];
    __shared__ float Bs[16][128];
    const int tid = threadIdx.x;
    const int tx = tid & 15;
    const int ty = tid >> 4;
    const int bm = blockIdx.x * 64;

    float acc[8][8];
#pragma unroll
    for (int i = 0; i < 8; i++)
#pragma unroll
        for (int j = 0; j < 8; j++) acc[i][j] = 0.f;

    const int K = K0 + K1;
    for (int kc = 0; kc < K; kc += 16) {
        const bool first = (kc < K0);
        const float* A = first ? A0 : A1;
        const float* W = first ? W0 : W1;
        const int kb = first ? kc : kc - K0;
        const int lda = first ? K0 : K1;
        // load A tile (64x16), store transposed
#pragma unroll
        for (int i = 0; i < 2; i++) {
            int idx = tid * 2 + i;        // 0..255 float4 slots
            int row = idx >> 2;
            int c4 = (idx & 3) * 4;
            float4 v = make_float4(0.f, 0.f, 0.f, 0.f);
            int gr = bm + row;
            if (gr < M) v = *(const float4*)(A + (size_t)gr * lda + kb + c4);
            As[c4 + 0][row] = v.x;
            As[c4 + 1][row] = v.y;
            As[c4 + 2][row] = v.z;
            As[c4 + 3][row] = v.w;
        }
        // load W tile (16x128)
#pragma unroll
        for (int i = 0; i < 4; i++) {
            int idx = i * 128 + tid;
            int row = idx >> 5;
            int col = (idx & 31) * 4;
            *(float4*)&Bs[row][col] = *(const float4*)(W + (size_t)(kb + row) * 128 + col);
        }
        __syncthreads();
#pragma unroll
        for (int kk = 0; kk < 16; kk++) {
            float a[8], b[8];
            *(float4*)&a[0] = *(const float4*)&As[kk][ty * 8];
            *(float4*)&a[4] = *(const float4*)&As[kk][ty * 8 + 4];
            *(float4*)&b[0] = *(const float4*)&Bs[kk][tx * 8];
            *(float4*)&b[4] = *(const float4*)&Bs[kk][tx * 8 + 4];
#pragma unroll
            for (int i = 0; i < 8; i++)
#pragma unroll
                for (int j = 0; j < 8; j++)
                    acc[i][j] += a[i] * b[j];
        }
        __syncthreads();
    }
#pragma unroll
    for (int i = 0; i < 8; i++) {
        int gr = bm + ty * 8 + i;
        if (gr >= M) continue;
        float* crow = C + (size_t)gr * 128 + tx * 8;
        float4 o0, o1;
        o0.x = apply_epi(acc[i][0], epi); o0.y = apply_epi(acc[i][1], epi);
        o0.z = apply_epi(acc[i][2], epi); o0.w = apply_epi(acc[i][3], epi);
        o1.x = apply_epi(acc[i][4], epi); o1.y = apply_epi(acc[i][5], epi);
        o1.z = apply_epi(acc[i][6], epi); o1.w = apply_epi(acc[i][7], epi);
        *(float4*)(crow + 0) = o0;
        *(float4*)(crow + 4) = o1;
    }
}

// ---------------- attention score + segment max ----------------
__global__ void score_k(const int* __restrict__ src, const int* __restrict__ dst,
                        const float* __restrict__ q, const float* __restrict__ kb,
                        float* __restrict__ score, unsigned* __restrict__ menc) {
    long t = (long)blockIdx.x * blockDim.x + threadIdx.x;
    int e = (int)(t >> 5), lane = (int)(t & 31);
    if (e >= Ee) return;
    int s = src[e], d = dst[e];
    float4 qv = *(const float4*)(q + (size_t)d * HIDd + lane * 4);
    float4 kv = *(const float4*)(kb + (size_t)s * HIDd + lane * 4);
    float p = qv.x * kv.x + qv.y * kv.y + qv.z * kv.z + qv.w * kv.w;
#pragma unroll
    for (int off = 16; off; off >>= 1) p += __shfl_xor_sync(0xffffffffu, p, off);
    if (lane == 0) {
        p *= 0.08838834764831845f;          // 1/sqrt(128)
        p = p > 0.f ? p : SLOPE * p;        // leaky relu
        score[e] = p;
        atomicMax(menc + d, flipf(p));
    }
}

// ---------------- exp(score - m) + segment sum ----------------
__global__ void ex_k(const int* __restrict__ dst, float* __restrict__ score,
                     const unsigned* __restrict__ menc, float* __restrict__ den) {
    int e = blockIdx.x * blockDim.x + threadIdx.x;
    if (e >= Ee) return;
    int d = dst[e];
    float m = unflipf(menc[d]);
    if (!isfinite(m)) m = 0.0f;
    float exv = expf(score[e] - m);
    score[e] = exv;
    atomicAdd(den + d, exv);
}

// ---------------- alpha * v[src] scatter ----------------
__global__ void attn_k(const int* __restrict__ src, const int* __restrict__ dst,
                       const float* __restrict__ score, const float* __restrict__ den,
                       const float* __restrict__ v, float* __restrict__ attn) {
    long t = (long)blockIdx.x * blockDim.x + threadIdx.x;
    int e = (int)(t >> 5), c = (int)(t & 31);
    if (e >= Ee) return;
    int s = src[e], d = dst[e];
    float alpha = score[e] / fmaxf(den[d], 1e-9f);
    float4 vv = *(const float4*)(v + (size_t)s * HIDd + c * 4);
    float* o = attn + (size_t)d * HIDd + c * 4;
    atomicAdd(o + 0, alpha * vv.x); atomicAdd(o + 1, alpha * vv.y);
    atomicAdd(o + 2, alpha * vv.z); atomicAdd(o + 3, alpha * vv.w);
}

// ---------------- final: logits = (hn2+attn) @ W_out[128x64]; log_softmax ----------------
__global__ void __launch_bounds__(256) final_k(const float* __restrict__ hn2,
                                               const float* __restrict__ attn,
                                               const float* __restrict__ Wout,
                                               float* __restrict__ out) {
    __shared__ float sW[128 * 64];
    __shared__ float srow[8][128];
    int tid = threadIdx.x;
#pragma unroll
    for (int i = 0; i < 32; i++) sW[tid + i * 256] = Wout[tid + i * 256];
    __syncthreads();

    int w = tid >> 5, lane = tid & 31;
    int n = blockIdx.x * 8 + w;
    if (n >= Nn) return;

    float4 a = *(const float4*)(hn2 + (size_t)n * 128 + lane * 4);
    float4 b = *(const float4*)(attn + (size_t)n * 128 + lane * 4);
    float4 r = make_float4(a.x + b.x, a.y + b.y, a.z + b.z, a.w + b.w);
    *(float4*)&srow[w][lane * 4] = r;
    __syncwarp();

    float acc0 = 0.f, acc1 = 0.f;
#pragma unroll 8
    for (int k = 0; k < 128; k++) {
        float rv = srow[w][k];
        acc0 += rv * sW[k * 64 + lane];
        acc1 += rv * sW[k * 64 + lane + 32];
    }
    float mx = fmaxf(acc0, acc1);
#pragma unroll
    for (int off = 16; off; off >>= 1) mx = fmaxf(mx, __shfl_xor_sync(0xffffffffu, mx, off));
    float sm = expf(acc0 - mx) + expf(acc1 - mx);
#pragma unroll
    for (int off = 16; off; off >>= 1) sm += __shfl_xor_sync(0xffffffffu, sm, off);
    float ls = logf(sm);
    out[(size_t)n * 64 + lane] = acc0 - mx - ls;
    out[(size_t)n * 64 + lane + 32] = acc1 - mx - ls;
}

// ---------------- host ----------------
#define SYMADDR(p, s) do { void* _t = nullptr; cudaGetSymbolAddress(&_t, s); (p) = (decltype(p))_t; } while (0)

static inline void zero_buf(float* p, size_t nfloats) {
    long n4 = (long)(nfloats / 4);
    zero_k<<<(int)((n4 + 255) / 256), 256>>>(p, n4);
}

extern "C" void kernel_launch(void* const* d_in, const int* in_sizes, int n_in,
                              void* d_out, int out_size) {
    const float* x   = (const float*)d_in[0];
    const float* et  = (const float*)d_in[1];
    const int*   H   = (const int*)d_in[2];
    const int*   rei = (const int*)d_in[3];
    const int*   lg  = (const int*)d_in[4];
    const float* W_tsa1_s = (const float*)d_in[5];
    const float* W_tsa1_n = (const float*)d_in[6];
    const float* W_tsa2_s = (const float*)d_in[7];
    const float* W_tsa2_n = (const float*)d_in[8];
    const float* W_etn    = (const float*)d_in[9];
    const float* W_eg_lin = (const float*)d_in[10];
    const float* W_ea_s   = (const float*)d_in[11];
    const float* W_ea_n   = (const float*)d_in[12];
    const float* W_an1_s  = (const float*)d_in[13];
    const float* W_an1_n  = (const float*)d_in[14];
    const float* W_an2_s  = (const float*)d_in[15];
    const float* W_an2_n  = (const float*)d_in[16];
    const float* Wq       = (const float*)d_in[17];
    const float* Wk       = (const float*)d_in[18];
    const float* Wv       = (const float*)d_in[19];
    const float* W_out    = (const float*)d_in[20];
    float* out = (float*)d_out;

    const int* H0 = H,        * H1 = H + Ee;
    const int* rsrc = rei,    * rdst = rei + Ee;
    const int* lsrc = lg,     * ldst = lg + LGEe;

    float *b_deg_lg, *b_aggT, *b_h1, *b_agg1, *b_h2, *b_deg_raw, *b_degN, *b_aggN,
          *b_tmp, *b_edge_repr, *b_aggr_edge, *b_xws, *b_xwn, *b_hn1, *b_hn2,
          *b_q, *b_k, *b_v, *b_attn, *b_score, *b_den;
    unsigned* b_menc;
    SYMADDR(b_deg_lg, B_deg_lg);   SYMADDR(b_aggT, B_aggT);
    SYMADDR(b_h1, B_h1);           SYMADDR(b_agg1, B_agg1);
    SYMADDR(b_h2, B_h2);           SYMADDR(b_deg_raw, B_deg_raw);
    SYMADDR(b_degN, B_degN);       SYMADDR(b_aggN, B_aggN);
    SYMADDR(b_tmp, B_tmp);         SYMADDR(b_edge_repr, B_edge_repr);
    SYMADDR(b_aggr_edge, B_aggr_edge);
    SYMADDR(b_xws, B_xws);         SYMADDR(b_xwn, B_xwn);
    SYMADDR(b_hn1, B_hn1);         SYMADDR(b_hn2, B_hn2);
    SYMADDR(b_q, B_q);             SYMADDR(b_k, B_k);
    SYMADDR(b_v, B_v);             SYMADDR(b_attn, B_attn);
    SYMADDR(b_score, B_score);     SYMADDR(b_menc, B_menc);
    SYMADDR(b_den, B_den);

    const int TB = 256;
    const int gridE_gemm = (Ee + 63) / 64;
    const int gridN_gemm = (Nn + 63) / 64;

    // ---- TSA layer 1 on line graph ----
    zero_buf(b_aggT, (size_t)Ee * Tt);
    zero_buf(b_deg_lg, Ee);
    lg_agg64_k<<<(int)(((long)LGEe * 16 + TB - 1) / TB), TB>>>(lsrc, ldst, et, b_aggT, b_deg_lg);
    scale_k<<<(int)(((long)Ee * Tt / 4 + TB - 1) / TB), TB>>>(b_aggT, b_deg_lg, Ee, Tt);
    gemm_k<<<gridE_gemm, 128>>>(et, Tt, W_tsa1_s, b_aggT, Tt, W_tsa1_n, b_h1, Ee, 1 /*relu*/);

    // ---- TSA layer 2 on line graph ----
    zero_buf(b_agg1, (size_t)Ee * HIDd);
    agg128_k<<<(int)(((long)LGEe * 32 + TB - 1) / TB), TB>>>(lsrc, ldst, b_h1, b_agg1, LGEe);
    scale_k<<<(int)(((long)Ee * HIDd / 4 + TB - 1) / TB), TB>>>(b_agg1, b_deg_lg, Ee, HIDd);
    gemm_k<<<gridE_gemm, 128>>>(b_h1, HIDd, W_tsa2_s, b_agg1, HIDd, W_tsa2_n, b_h2, Ee, 0);

    // ---- EdgeToNodeConv + EdgeGCN linear ----
    zero_buf(b_aggN, (size_t)Nn * HIDd);
    zero_buf(b_degN, Nn);
    e2n_agg_k<<<(int)(((long)Ee * 32 + TB - 1) / TB), TB>>>(H0, H1, b_h2, b_aggN, b_degN);
    scale_k<<<(int)(((long)Nn * HIDd / 4 + TB - 1) / TB), TB>>>(b_aggN, b_degN, Nn, HIDd);
    gemm_k<<<gridN_gemm, 128>>>(b_aggN, HIDd, W_etn, nullptr, 0, nullptr, b_tmp, Nn, 2 /*leaky*/);
    gemm_k<<<gridN_gemm, 128>>>(b_tmp, HIDd, W_eg_lin, nullptr, 0, nullptr, b_edge_repr, Nn, 0);

    // ---- raw-graph degree (shared by all raw-graph SAGE layers) ----
    zero_buf(b_deg_raw, Nn);
    deg_k<<<(Ee + TB - 1) / TB, TB>>>(rdst, b_deg_raw, Ee);

    // ---- edge_aggr SAGE ----
    zero_buf(b_aggN, (size_t)Nn * HIDd);
    agg128_k<<<(int)(((long)Ee * 32 + TB - 1) / TB), TB>>>(rsrc, rdst, b_edge_repr, b_aggN, Ee);
    scale_k<<<(int)(((long)Nn * HIDd / 4 + TB - 1) / TB), TB>>>(b_aggN, b_deg_raw, Nn, HIDd);
    gemm_k<<<gridN_gemm, 128>>>(b_edge_repr, HIDd, W_ea_s, b_aggN, HIDd, W_ea_n, b_aggr_edge, Nn, 0);

    // ---- attr_node_model layer 1 (transform-first: mean is linear) ----
    gemm_k<<<gridN_gemm, 128>>>(x, FNODE, W_an1_s, nullptr, 0, nullptr, b_xws, Nn, 0);
    gemm_k<<<gridN_gemm, 128>>>(x, FNODE, W_an1_n, nullptr, 0, nullptr, b_xwn, Nn, 0);
    zero_buf(b_aggN, (size_t)Nn * HIDd);
    agg128_k<<<(int)(((long)Ee * 32 + TB - 1) / TB), TB>>>(rsrc, rdst, b_xwn, b_aggN, Ee);
    scale_k<<<(int)(((long)Nn * HIDd / 4 + TB - 1) / TB), TB>>>(b_aggN, b_deg_raw, Nn, HIDd);
    addrelu_k<<<(int)(((long)Nn * HIDd / 4 + TB - 1) / TB), TB>>>(b_xws, b_aggN, b_hn1, (long)Nn * HIDd / 4);

    // ---- attr_node_model layer 2 ----
    zero_buf(b_aggN, (size_t)Nn * HIDd);
    agg128_k<<<(int)(((long)Ee * 32 + TB - 1) / TB), TB>>>(rsrc, rdst, b_hn1, b_aggN, Ee);
    scale_k<<<(int)(((long)Nn * HIDd / 4 + TB - 1) / TB), TB>>>(b_aggN, b_deg_raw, Nn, HIDd);
    gemm_k<<<gridN_gemm, 128>>>(b_hn1, HIDd, W_an2_s, b_aggN, HIDd, W_an2_n, b_hn2, Nn, 0);

    // ---- MixAttention projections ----
    gemm_k<<<gridN_gemm, 128>>>(b_hn2, HIDd, Wq, nullptr, 0, nullptr, b_q, Nn, 0);
    gemm_k<<<gridN_gemm, 128>>>(b_aggr_edge, HIDd, Wk, nullptr, 0, nullptr, b_k, Nn, 0);
    gemm_k<<<gridN_gemm, 128>>>(b_aggr_edge, HIDd, Wv, nullptr, 0, nullptr, b_v, Nn, 0);

    // ---- attention softmax over incoming edges ----
    zero_buf((float*)b_menc, Nn);   // 0 encodes "below all real floats"
    zero_buf(b_den, Nn);
    zero_buf(b_attn, (size_t)Nn * HIDd);
    score_k<<<(int)(((long)Ee * 32 + TB - 1) / TB), TB>>>(rsrc, rdst, b_q, b_k, b_score, b_menc);
    ex_k<<<(Ee + TB - 1) / TB, TB>>>(rdst, b_score, b_menc, b_den);
    attn_k<<<(int)(((long)Ee * 32 + TB - 1) / TB), TB>>>(rsrc, rdst, b_score, b_den, b_v, b_attn);

    // ---- classifier + log_softmax ----
    final_k<<<(Nn + 7) / 8, 256>>>(b_hn2, b_attn, W_out, out);
}